// round 11
// baseline (speedup 1.0000x reference)
#include <cuda_runtime.h>
#include <math.h>
#include <stdint.h>

#define MAXN 100352          // padded N (N = 100000)
#define BMAX 2048
#define DHC  256
#define D2HC 512
#define EPSV 1e-6f
#define GS   16

typedef unsigned long long u64;

// ---------------- device scratch ----------------
__device__ float d_zh[MAXN * DHC];     // z_h
__device__ float d_mh[MAXN * DHC];     // mh = h @ W_mu (raw)
__device__ float d_a1[MAXN * D2HC];    // tanh(z_h @ W_r1)
__device__ float d_wc[D2HC * DHC];     // Wc = W_r2 @ W_mu
__device__ float d_zp[MAXN * 3];
__device__ float d_tgtp[MAXN * 3];
__device__ float d_eps2[MAXN * 3];

__device__ float d_gpar[BMAX * GS];
__device__ float d_accA[BMAX * 16];
__device__ float d_finA[BMAX * 16];
__device__ float d_accB[BMAX * 16];
__device__ float d_finB[BMAX * 16];
__device__ float d_accC[BMAX * 8];
__device__ float d_finC[BMAX * 8];
__device__ int   d_start[BMAX + 1];
__device__ double d_lossH, d_lossP;

// ---------------- packed f32x2 helpers ----------------
__device__ __forceinline__ void ffma2(u64 &d, u64 a, u64 b) {
    asm("fma.rn.f32x2 %0, %1, %2, %0;" : "+l"(d) : "l"(a), "l"(b));
}
__device__ __forceinline__ u64 dup2(float x) {
    u64 r;
    asm("mov.b64 %0, {%1, %1};" : "=l"(r) : "r"(__float_as_uint(x)));
    return r;
}
__device__ __forceinline__ float2 unpk(u64 v) {
    float2 f;
    asm("mov.b64 {%0, %1}, %2;" : "=f"(f.x), "=f"(f.y) : "l"(v));
    return f;
}

// ---------------- SGEMM core: 128x64 tile, BK=16, 256 thr, 8x4/thread ----
// Rows: ty=tid>>4 (0..15), SPLIT 4+4: {ty*4+i, 64+ty*4+i}. Cols: tx=tid&15 -> tx*4..+3.
// acc2[i][j]: row i (split order), column pair j (cols 2j,2j+1 of the 4).
#define ASTR 132   // padded A row stride (floats)

__device__ __forceinline__ void sgemm_body(
    const float* __restrict__ A, const float* __restrict__ Bm,
    int Nrows, int K, int ncols, u64 acc2[8][2])
{
    __shared__ __align__(16) float As[16 * ASTR];   // [k][m], padded
    __shared__ __align__(16) float Bs[16 * 64];     // [k][n]

    const int tid = threadIdx.x;
    const int ty = tid >> 4, tx = tid & 15;
    const int row0 = blockIdx.y * 128;
    const int col0 = blockIdx.x * 64;

    #pragma unroll
    for (int i = 0; i < 8; i++)
        #pragma unroll
        for (int j = 0; j < 2; j++) acc2[i][j] = 0ULL;

    const int nk = K >> 4;
    const int ac  = (tid & 3) << 2;    // A: k-chunk within tile
    const int arB = tid >> 2;          // A: row base 0..63 (+64 for p=1)
    const int bkr = tid >> 4;          // B: k-row 0..15
    const int bcc = (tid & 15) << 2;   // B: col 0..60

    float4 pa[2], pb;

    auto gload = [&](int kt) {
        #pragma unroll
        for (int p = 0; p < 2; p++) {
            int r = arB + p * 64;
            pa[p] = (row0 + r < Nrows)
                ? *(const float4*)(A + (size_t)(row0 + r) * K + kt * 16 + ac)
                : make_float4(0.f, 0.f, 0.f, 0.f);
        }
        pb = *(const float4*)(Bm + (size_t)(kt * 16 + bkr) * ncols + col0 + bcc);
    };
    auto sstore = [&]() {
        #pragma unroll
        for (int p = 0; p < 2; p++) {
            int r = arB + p * 64;
            As[(ac + 0) * ASTR + r] = pa[p].x;
            As[(ac + 1) * ASTR + r] = pa[p].y;
            As[(ac + 2) * ASTR + r] = pa[p].z;
            As[(ac + 3) * ASTR + r] = pa[p].w;
        }
        *(float4*)&Bs[bkr * 64 + bcc] = pb;
    };

    gload(0); sstore();
    __syncthreads();

    for (int kt = 0; kt < nk; kt++) {
        if (kt + 1 < nk) gload(kt + 1);
        #pragma unroll
        for (int k = 0; k < 16; k++) {
            float4 a0 = *(const float4*)&As[k * ASTR + ty * 4];
            float4 a1 = *(const float4*)&As[k * ASTR + 64 + ty * 4];
            ulonglong2 b0 = *(const ulonglong2*)&Bs[k * 64 + tx * 4];
            u64 bp[2] = {b0.x, b0.y};
            float av[8] = {a0.x, a0.y, a0.z, a0.w, a1.x, a1.y, a1.z, a1.w};
            #pragma unroll
            for (int i = 0; i < 8; i++) {
                u64 ad = dup2(av[i]);
                ffma2(acc2[i][0], ad, bp[0]);
                ffma2(acc2[i][1], ad, bp[1]);
            }
        }
        if (kt + 1 < nk) {
            __syncthreads();
            sstore();
            __syncthreads();
        }
    }
}

// epilogue row helper (split 4+4 mapping)
#define EPI_ROW(i)  (row0 + ((i) < 4 ? ty * 4 + (i) : 64 + ty * 4 + (i) - 4))

__device__ __forceinline__ float4 acc_row(const u64 acc2[8][2], int i) {
    float2 c0 = unpk(acc2[i][0]), c1 = unpk(acc2[i][1]);
    return make_float4(c0.x, c0.y, c1.x, c1.y);
}

// ---------------- GEMM kernels with fused epilogues ----------------
// GEMMW: Wc = W_r2 @ W_mu  (512x256 out -> grid 4x4)
__global__ void __launch_bounds__(256, 3) k_gemmW(
    const float* __restrict__ Wr2, const float* __restrict__ Wmu)
{
    u64 acc2[8][2];
    sgemm_body(Wr2, Wmu, D2HC, DHC, DHC, acc2);
    const int ty = threadIdx.x >> 4, tx = threadIdx.x & 15;
    const int row0 = blockIdx.y * 128, cb = blockIdx.x * 64 + tx * 4;
    #pragma unroll
    for (int i = 0; i < 8; i++) {
        int r = EPI_ROW(i);
        *(float4*)(d_wc + (size_t)r * DHC + cb) = acc_row(acc2, i);
    }
}

// GEMM1: mh = h @ W_mu (stored raw); z_h = mh*(1-t) + sig*eps_h
__global__ void __launch_bounds__(256, 3) k_gemm1(
    const float* __restrict__ h, const float* __restrict__ Wmu,
    const float* __restrict__ eh, const int* __restrict__ idx, int N)
{
    u64 acc2[8][2];
    sgemm_body(h, Wmu, N, DHC, DHC, acc2);
    const int ty = threadIdx.x >> 4, tx = threadIdx.x & 15;
    const int row0 = blockIdx.y * 128, cb = blockIdx.x * 64 + tx * 4;
    #pragma unroll
    for (int i = 0; i < 8; i++) {
        int r = EPI_ROW(i);
        if (r >= N) continue;
        int b = idx[r];
        float omt = d_gpar[b*GS+1], sig = d_gpar[b*GS+2];
        float4 m = acc_row(acc2, i);
        *(float4*)(d_mh + (size_t)r * DHC + cb) = m;
        float4 e = *(const float4*)(eh + (size_t)r * DHC + cb);
        float4 o;
        o.x = m.x*omt + sig*e.x; o.y = m.y*omt + sig*e.y;
        o.z = m.z*omt + sig*e.z; o.w = m.w*omt + sig*e.w;
        *(float4*)(d_zh + (size_t)r * DHC + cb) = o;
    }
}

// GEMM2: a1 = tanh(z_h @ W_r1)
__global__ void __launch_bounds__(256, 3) k_gemm2(
    const float* __restrict__ Wr1, int N)
{
    u64 acc2[8][2];
    sgemm_body(d_zh, Wr1, N, DHC, D2HC, acc2);
    const int ty = threadIdx.x >> 4, tx = threadIdx.x & 15;
    const int row0 = blockIdx.y * 128, cb = blockIdx.x * 64 + tx * 4;
    #pragma unroll
    for (int i = 0; i < 8; i++) {
        int r = EPI_ROW(i);
        if (r >= N) continue;
        float4 v = acc_row(acc2, i);
        float4 o;
        o.x = tanhf(v.x); o.y = tanhf(v.y);
        o.z = tanhf(v.z); o.w = tanhf(v.w);
        *(float4*)(d_a1 + (size_t)r * D2HC + cb) = o;
    }
}

// GEMM34: E = a1 @ Wc; loss += sum(s^2 * (mh - E)^2)
__global__ void __launch_bounds__(256, 3) k_gemm34(
    const int* __restrict__ idx, int N)
{
    u64 acc2[8][2];
    sgemm_body(d_a1, d_wc, N, D2HC, DHC, acc2);
    const int ty = threadIdx.x >> 4, tx = threadIdx.x & 15;
    const int row0 = blockIdx.y * 128, cb = blockIdx.x * 64 + tx * 4;
    float local = 0.f;
    #pragma unroll
    for (int i = 0; i < 8; i++) {
        int r = EPI_ROW(i);
        if (r >= N) continue;
        int b = idx[r];
        float s = d_gpar[b*GS+8];
        float4 v = acc_row(acc2, i);
        float4 m = *(const float4*)(d_mh + (size_t)r * DHC + cb);
        float v0 = m.x - v.x, v1 = m.y - v.y, v2 = m.z - v.z, v3 = m.w - v.w;
        local += s * s * (v0*v0 + v1*v1 + v2*v2 + v3*v3);
    }
    __shared__ float red[256];
    __syncthreads();
    red[threadIdx.x] = local;
    __syncthreads();
    for (int off = 128; off > 0; off >>= 1) {
        if (threadIdx.x < off) red[threadIdx.x] += red[threadIdx.x + off];
        __syncthreads();
    }
    if (threadIdx.x == 0) atomicAdd(&d_lossH, (double)red[0]);
}

// ---------------- small helpers / setup ----------------
__device__ __forceinline__ float softplusf(float x) {
    return fmaxf(x, 0.f) + log1pf(expf(-fabsf(x)));
}
__device__ __forceinline__ void syminv3(const float s[6], float o[6]) {
    float s00=s[0], s01=s[1], s02=s[2], s11=s[3], s12=s[4], s22=s[5];
    float det = s00*(s11*s22 - s12*s12) - s01*(s01*s22 - s12*s02) + s02*(s01*s12 - s11*s02);
    float id = 1.f / det;
    o[0] = (s11*s22 - s12*s12)*id;
    o[1] = (s02*s12 - s01*s22)*id;
    o[2] = (s01*s12 - s02*s11)*id;
    o[3] = (s00*s22 - s02*s02)*id;
    o[4] = (s01*s02 - s00*s12)*id;
    o[5] = (s00*s11 - s01*s01)*id;
}
__device__ __forceinline__ void symmv(const float m[6], const float v[3], float o[3]) {
    o[0] = m[0]*v[0] + m[1]*v[1] + m[2]*v[2];
    o[1] = m[1]*v[0] + m[3]*v[1] + m[4]*v[2];
    o[2] = m[2]*v[0] + m[4]*v[1] + m[5]*v[2];
}
template<int NC>
__device__ __forceinline__ void block_reduce_store(const float* vals, float* gout) {
    __shared__ float sh[NC][64];
    int tid = threadIdx.x;
    #pragma unroll
    for (int c = 0; c < NC; c++) sh[c][tid] = vals[c];
    __syncthreads();
    #pragma unroll
    for (int off = 32; off > 0; off >>= 1) {
        if (tid < off) {
            #pragma unroll
            for (int c = 0; c < NC; c++) sh[c][tid] += sh[c][tid + off];
        }
        __syncthreads();
    }
    if (tid == 0) {
        #pragma unroll
        for (int c = 0; c < NC; c++) gout[c] = sh[c][0];
    }
}

__global__ void k_init(int B) {
    int i = blockIdx.x * blockDim.x + threadIdx.x;
    if (i < B * 16) { d_accA[i] = 0.f; d_accB[i] = 0.f; }
    if (i < B * 8)  { d_accC[i] = 0.f; }
    if (i == 0) { d_lossH = 0.0; d_lossP = 0.0; }
}

__global__ void k_scalars(const float* __restrict__ t,
                          const float* __restrict__ gph,
                          const float* __restrict__ gpp,
                          int B, int N) {
    int b = blockIdx.x * blockDim.x + threadIdx.x;
    if (b == 0) d_start[B] = N;
    if (b >= B) return;
    float tb  = t[b];
    float sph = softplusf(gph[0]);
    float spp = softplusf(gpp[0]);
    float gh  = 0.1f + sph * tb;
    float gp  = 0.1f + spp * tb;
    float sig = 0.1f + 0.9f * tb;
    float omt = 1.f - tb;
    float a   = 0.2f + 0.8f * tb;
    float bb  = 0.1f * tb;
    float s   = (1.f + (0.9f + 0.5f*gh*gh/sig) * omt / sig) / gh;
    float* g = &d_gpar[b * GS];
    g[0]=tb; g[1]=omt; g[2]=sig; g[3]=a; g[4]=bb; g[5]=1.f/a;
    g[6]=gp; g[7]=0.5f*gp*gp; g[8]=s;
}

__global__ void k_starts(const int* __restrict__ idx, int N) {
    int n = blockIdx.x * blockDim.x + threadIdx.x;
    if (n >= N) return;
    int b = idx[n];
    if (n == 0 || idx[n-1] != b) d_start[b] = n;
}

// ---------------- pos branch (unchanged, passing since R1) ----------------
__global__ void __launch_bounds__(64) k_posA(
    const float* __restrict__ pos, const float* __restrict__ ep)
{
    int b = blockIdx.x;
    int s0 = d_start[b], s1 = d_start[b+1];
    float a = d_gpar[b*GS+3], bb = d_gpar[b*GS+4], alpha = d_gpar[b*GS+5];
    float acc[15];
    #pragma unroll
    for (int c = 0; c < 15; c++) acc[c] = 0.f;
    for (int n = s0 + threadIdx.x; n < s1; n += 64) {
        float p0 = pos[3*n], p1 = pos[3*n+1], p2 = pos[3*n+2];
        float e0 = ep[3*n],  e1 = ep[3*n+1],  e2 = ep[3*n+2];
        float pn = sqrtf(p0*p0 + p1*p1 + p2*p2);
        float iv = 1.f / (pn + EPSV);
        float n0 = p0*iv, n1 = p1*iv, n2 = p2*iv;
        float nn = n0*n0 + n1*n1 + n2*n2;
        float beta = -bb / (a * (a + bb * nn));
        float nde = n0*e0 + n1*e1 + n2*e2;
        acc[0] += beta*n0*n0; acc[1] += beta*n0*n1; acc[2] += beta*n0*n2;
        acc[3] += beta*n1*n1; acc[4] += beta*n1*n2; acc[5] += beta*n2*n2;
        acc[6]  += alpha*e0 + beta*nde*n0;
        acc[7]  += alpha*e1 + beta*nde*n1;
        acc[8]  += alpha*e2 + beta*nde*n2;
        acc[9]  += a*e0 + bb*nde*n0;
        acc[10] += a*e1 + bb*nde*n1;
        acc[11] += a*e2 + bb*nde*n2;
        acc[12] += 0.8f*e0 + 0.1f*nde*n0;
        acc[13] += 0.8f*e1 + 0.1f*nde*n1;
        acc[14] += 0.8f*e2 + 0.1f*nde*n2;
    }
    block_reduce_store<15>(acc, &d_accA[b * 16]);
}

__global__ void k_finA(int B) {
    int b = blockIdx.x * blockDim.x + threadIdx.x;
    if (b >= B) return;
    float cnt = (float)(d_start[b+1] - d_start[b]);
    float alpha = d_gpar[b*GS+5];
    const float* A = &d_accA[b * 16];
    float S[6] = {A[0] + cnt*alpha, A[1], A[2], A[3] + cnt*alpha, A[4], A[5] + cnt*alpha};
    float iV[6]; syminv3(S, iV);
    float yb[3] = {A[6], A[7], A[8]};
    float w[3];  symmv(iV, yb, w);
    float* F = &d_finA[b * 16];
    F[0]=w[0]; F[1]=w[1]; F[2]=w[2];
    F[3]=A[9]/cnt;  F[4]=A[10]/cnt; F[5]=A[11]/cnt;
    F[6]=A[12]/cnt; F[7]=A[13]/cnt; F[8]=A[14]/cnt;
}

__global__ void __launch_bounds__(64) k_posB(
    const float* __restrict__ pos, const float* __restrict__ ep)
{
    int b = blockIdx.x;
    int s0 = d_start[b], s1 = d_start[b+1];
    const float* G = &d_gpar[b*GS];
    float omt = G[1], sig = G[2], a = G[3], bb = G[4], alpha = G[5], gph2 = G[7];
    const float* F = &d_finA[b*16];
    float w0=F[0], w1=F[1], w2_=F[2];
    float mUe0=F[3], mUe1=F[4], mUe2=F[5];
    float mdU0=F[6], mdU1=F[7], mdU2=F[8];
    float acc[9];
    #pragma unroll
    for (int c = 0; c < 9; c++) acc[c] = 0.f;
    for (int n = s0 + threadIdx.x; n < s1; n += 64) {
        float p0 = pos[3*n], p1 = pos[3*n+1], p2 = pos[3*n+2];
        float e0 = ep[3*n],  e1 = ep[3*n+1],  e2 = ep[3*n+2];
        float pn = sqrtf(p0*p0 + p1*p1 + p2*p2);
        float iv = 1.f / (pn + EPSV);
        float n0 = p0*iv, n1 = p1*iv, n2 = p2*iv;
        float nn = n0*n0 + n1*n1 + n2*n2;
        float beta = -bb / (a * (a + bb * nn));
        float nde = n0*e0 + n1*e1 + n2*e2;
        float y0 = alpha*e0 + beta*nde*n0, y1 = alpha*e1 + beta*nde*n1, y2 = alpha*e2 + beta*nde*n2;
        float Ue0 = a*e0 + bb*nde*n0, Ue1 = a*e1 + bb*nde*n1, Ue2 = a*e2 + bb*nde*n2;
        float dU0 = 0.8f*e0 + 0.1f*nde*n0, dU1 = 0.8f*e1 + 0.1f*nde*n1, dU2v = 0.8f*e2 + 0.1f*nde*n2;
        float zp0 = omt*p0 + Ue0 - mUe0;
        float zp1 = omt*p1 + Ue1 - mUe1;
        float zp2 = omt*p2 + Ue2 - mUe2;
        d_zp[3*n]=zp0; d_zp[3*n+1]=zp1; d_zp[3*n+2]=zp2;
        float ndw = n0*w0 + n1*w1 + n2*w2_;
        float iw0 = alpha*w0 + beta*ndw*n0, iw1 = alpha*w1 + beta*ndw*n1, iw2 = alpha*w2_ + beta*ndw*n2;
        d_tgtp[3*n]   = -p0 + dU0  - mdU0 - gph2*(iw0 - y0);
        d_tgtp[3*n+1] = -p1 + dU1  - mdU1 - gph2*(iw1 - y1);
        d_tgtp[3*n+2] = -p2 + dU2v - mdU2 - gph2*(iw2 - y2);
        float pr0 = 0.9f*zp0, pr1 = 0.9f*zp1, pr2 = 0.9f*zp2;
        float rl0 = sig*zp0,  rl1 = sig*zp1,  rl2 = sig*zp2;
        float prn = sqrtf(pr0*pr0 + pr1*pr1 + pr2*pr2);
        float iv2 = 1.f / (prn + EPSV);
        float m0 = pr0*iv2, m1 = pr1*iv2, m2 = pr2*iv2;
        float mm = m0*m0 + m1*m1 + m2*m2;
        float beta2 = -bb / (a * (a + bb * mm));
        float ndp = m0*rl0 + m1*rl1 + m2*rl2;
        acc[0] += beta2*m0*m0; acc[1] += beta2*m0*m1; acc[2] += beta2*m0*m2;
        acc[3] += beta2*m1*m1; acc[4] += beta2*m1*m2; acc[5] += beta2*m2*m2;
        acc[6] += (alpha - 1.f)*rl0 + beta2*ndp*m0;
        acc[7] += (alpha - 1.f)*rl1 + beta2*ndp*m1;
        acc[8] += (alpha - 1.f)*rl2 + beta2*ndp*m2;
    }
    block_reduce_store<9>(acc, &d_accB[b * 16]);
}

__global__ void k_finB(int B) {
    int b = blockIdx.x * blockDim.x + threadIdx.x;
    if (b >= B) return;
    float cnt = (float)(d_start[b+1] - d_start[b]);
    float alpha = d_gpar[b*GS+5];
    const float* A = &d_accB[b * 16];
    float S[6] = {A[0] + cnt*alpha, A[1], A[2], A[3] + cnt*alpha, A[4], A[5] + cnt*alpha};
    float iV[6]; syminv3(S, iV);
    float q[3] = {A[6], A[7], A[8]};
    float c[3]; symmv(iV, q, c);
    float* F = &d_finB[b * 16];
    F[0]=iV[0]; F[1]=iV[1]; F[2]=iV[2]; F[3]=iV[3]; F[4]=iV[4]; F[5]=iV[5];
    F[6]=c[0];  F[7]=c[1];  F[8]=c[2];
}

__global__ void __launch_bounds__(64) k_posC()
{
    int b = blockIdx.x;
    int s0 = d_start[b], s1 = d_start[b+1];
    const float* G = &d_gpar[b*GS];
    float sig = G[2], a = G[3], bb = G[4], alpha = G[5];
    const float* F = &d_finB[b*16];
    float c0 = F[6], c1 = F[7], c2 = F[8];
    float acc[6];
    #pragma unroll
    for (int c = 0; c < 6; c++) acc[c] = 0.f;
    for (int n = s0 + threadIdx.x; n < s1; n += 64) {
        float zp0 = d_zp[3*n], zp1 = d_zp[3*n+1], zp2 = d_zp[3*n+2];
        float pr0 = 0.9f*zp0, pr1 = 0.9f*zp1, pr2 = 0.9f*zp2;
        float prn = sqrtf(pr0*pr0 + pr1*pr1 + pr2*pr2);
        float iv = 1.f / (prn + EPSV);
        float m0 = pr0*iv, m1 = pr1*iv, m2 = pr2*iv;
        float mm = m0*m0 + m1*m1 + m2*m2;
        float beta2 = -bb / (a * (a + bb * mm));
        float v0 = sig*zp0 - c0, v1 = sig*zp1 - c1, v2 = sig*zp2 - c2;
        float ndv = m0*v0 + m1*v1 + m2*v2;
        float e0 = alpha*v0 + beta2*ndv*m0;
        float e1 = alpha*v1 + beta2*ndv*m1;
        float e2 = alpha*v2 + beta2*ndv*m2;
        d_eps2[3*n]=e0; d_eps2[3*n+1]=e1; d_eps2[3*n+2]=e2;
        float nde = m0*e0 + m1*e1 + m2*e2;
        acc[0] += alpha*e0 + beta2*nde*m0;
        acc[1] += alpha*e1 + beta2*nde*m1;
        acc[2] += alpha*e2 + beta2*nde*m2;
        acc[3] += 0.8f*e0 + 0.1f*nde*m0;
        acc[4] += 0.8f*e1 + 0.1f*nde*m1;
        acc[5] += 0.8f*e2 + 0.1f*nde*m2;
    }
    block_reduce_store<6>(acc, &d_accC[b * 8]);
}

__global__ void k_finC(int B) {
    int b = blockIdx.x * blockDim.x + threadIdx.x;
    if (b >= B) return;
    float cnt = (float)(d_start[b+1] - d_start[b]);
    const float* iV = &d_finB[b * 16];
    const float* A = &d_accC[b * 8];
    float yb[3] = {A[0], A[1], A[2]};
    float w2[3]; symmv(iV, yb, w2);
    float* F = &d_finC[b * 8];
    F[0]=w2[0]; F[1]=w2[1]; F[2]=w2[2];
    F[3]=A[3]/cnt; F[4]=A[4]/cnt; F[5]=A[5]/cnt;
}

__global__ void __launch_bounds__(64) k_posD()
{
    int b = blockIdx.x;
    int s0 = d_start[b], s1 = d_start[b+1];
    const float* G = &d_gpar[b*GS];
    float a = G[3], bb = G[4], alpha = G[5], gp = G[6], gph2 = G[7];
    float igp = 1.f / gp;
    const float* F = &d_finC[b*8];
    float w0=F[0], w1=F[1], w2_=F[2];
    float md0=F[3], md1=F[4], md2=F[5];
    float local = 0.f;
    for (int n = s0 + threadIdx.x; n < s1; n += 64) {
        float zp0 = d_zp[3*n], zp1 = d_zp[3*n+1], zp2 = d_zp[3*n+2];
        float e0 = d_eps2[3*n], e1 = d_eps2[3*n+1], e2 = d_eps2[3*n+2];
        float pr0 = 0.9f*zp0, pr1 = 0.9f*zp1, pr2 = 0.9f*zp2;
        float prn = sqrtf(pr0*pr0 + pr1*pr1 + pr2*pr2);
        float iv = 1.f / (prn + EPSV);
        float m0 = pr0*iv, m1 = pr1*iv, m2 = pr2*iv;
        float mm = m0*m0 + m1*m1 + m2*m2;
        float beta2 = -bb / (a * (a + bb * mm));
        float nde = m0*e0 + m1*e1 + m2*e2;
        float y0 = alpha*e0 + beta2*nde*m0, y1 = alpha*e1 + beta2*nde*m1, y2 = alpha*e2 + beta2*nde*m2;
        float du0 = 0.8f*e0 + 0.1f*nde*m0, du1 = 0.8f*e1 + 0.1f*nde*m1, du2 = 0.8f*e2 + 0.1f*nde*m2;
        float ndw = m0*w0 + m1*w1 + m2*w2_;
        float iw0 = alpha*w0 + beta2*ndw*m0, iw1 = alpha*w1 + beta2*ndw*m1, iw2 = alpha*w2_ + beta2*ndw*m2;
        float a0 = -pr0 + du0 - md0 - gph2*(iw0 - y0);
        float a1v = -pr1 + du1 - md1 - gph2*(iw1 - y1);
        float a2 = -pr2 + du2 - md2 - gph2*(iw2 - y2);
        float f0 = (a0  - d_tgtp[3*n])   * igp;
        float f1 = (a1v - d_tgtp[3*n+1]) * igp;
        float f2 = (a2  - d_tgtp[3*n+2]) * igp;
        local += f0*f0 + f1*f1 + f2*f2;
    }
    __shared__ float sh[64];
    sh[threadIdx.x] = local;
    __syncthreads();
    for (int off = 32; off > 0; off >>= 1) {
        if (threadIdx.x < off) sh[threadIdx.x] += sh[threadIdx.x + off];
        __syncthreads();
    }
    if (threadIdx.x == 0) atomicAdd(&d_lossP, (double)sh[0]);
}

__global__ void k_final(float* out, int N) {
    out[0] = (float)(d_lossH / ((double)N * 256.0));
    out[1] = (float)(d_lossP / ((double)N * 3.0));
}

// ---------------- launch ----------------
extern "C" void kernel_launch(void* const* d_in, const int* in_sizes, int n_in,
                              void* d_out, int out_size) {
    const float* t      = (const float*)d_in[0];
    const float* h      = (const float*)d_in[1];
    const float* pos    = (const float*)d_in[2];
    const float* eps_h  = (const float*)d_in[3];
    const float* eps_p  = (const float*)d_in[4];
    const float* gph    = (const float*)d_in[5];
    const float* gpp    = (const float*)d_in[6];
    const float* W_mu   = (const float*)d_in[7];
    const float* W_r1   = (const float*)d_in[8];
    const float* W_r2   = (const float*)d_in[9];
    const int*   idx    = (const int*)d_in[10];

    int B = in_sizes[0];
    int N = in_sizes[10];
    float* out = (float*)d_out;

    k_init<<<(B * 16 + 255) / 256, 256>>>(B);
    k_scalars<<<(B + 255) / 256, 256>>>(t, gph, gpp, B, N);
    k_starts<<<(N + 255) / 256, 256>>>(idx, N);

    // Wc = W_r2 @ W_mu  (512x256 output -> grid 4x4)
    k_gemmW<<<dim3(4, 4), 256>>>(W_r2, W_mu);

    int mt = (N + 127) / 128;
    k_gemm1<<<dim3(4, mt), 256>>>(h, W_mu, eps_h, idx, N);
    k_gemm2<<<dim3(8, mt), 256>>>(W_r1, N);
    k_gemm34<<<dim3(4, mt), 256>>>(idx, N);

    k_posA<<<B, 64>>>(pos, eps_p);
    k_finA<<<(B + 255) / 256, 256>>>(B);
    k_posB<<<B, 64>>>(pos, eps_p);
    k_finB<<<(B + 255) / 256, 256>>>(B);
    k_posC<<<B, 64>>>();
    k_finC<<<(B + 255) / 256, 256>>>(B);
    k_posD<<<B, 64>>>();

    k_final<<<1, 1>>>(out, N);
}

// round 12
// speedup vs baseline: 1.0907x; 1.0907x over previous
#include <cuda_runtime.h>
#include <math.h>
#include <stdint.h>

#define MAXN 100352          // padded N (N = 100000)
#define BMAX 2048
#define DHC  256
#define D2HC 512
#define EPSV 1e-6f
#define GS   16

typedef unsigned long long u64;

// ---------------- device scratch ----------------
__device__ float d_zh[MAXN * DHC];     // z_h
__device__ float d_mh[MAXN * DHC];     // mh = h @ W_mu (raw)
__device__ float d_a1[MAXN * D2HC];    // tanh(z_h @ W_r1)
__device__ float d_wc[D2HC * DHC];     // Wc = W_r2 @ W_mu
__device__ float d_zp[MAXN * 3];
__device__ float d_tgtp[MAXN * 3];
__device__ float d_eps2[MAXN * 3];

__device__ float d_gpar[BMAX * GS];
__device__ int   d_start[BMAX + 1];
__device__ double d_lossH, d_lossP;

// ---------------- packed f32x2 helpers ----------------
__device__ __forceinline__ void ffma2(u64 &d, u64 a, u64 b) {
    asm("fma.rn.f32x2 %0, %1, %2, %0;" : "+l"(d) : "l"(a), "l"(b));
}
__device__ __forceinline__ u64 dup2(float x) {
    u64 r;
    asm("mov.b64 %0, {%1, %1};" : "=l"(r) : "r"(__float_as_uint(x)));
    return r;
}
__device__ __forceinline__ float2 unpk(u64 v) {
    float2 f;
    asm("mov.b64 {%0, %1}, %2;" : "=f"(f.x), "=f"(f.y) : "l"(v));
    return f;
}

// ---------------- SGEMM core (R10/R7 winner, unchanged): 128x128, BK=16 ----
#define ASTR 132   // padded A row stride (floats)

__device__ __forceinline__ void sgemm_body(
    const float* __restrict__ A, const float* __restrict__ Bm,
    int Nrows, int K, int ncols, u64 acc2[8][4])
{
    __shared__ __align__(16) float As[16 * ASTR];   // [k][m], padded
    __shared__ __align__(16) float Bs[16 * 128];    // [k][n]

    const int tid = threadIdx.x;
    const int ty = tid >> 4, tx = tid & 15;
    const int row0 = blockIdx.y * 128;
    const int col0 = blockIdx.x * 128;

    #pragma unroll
    for (int i = 0; i < 8; i++)
        #pragma unroll
        for (int j = 0; j < 4; j++) acc2[i][j] = 0ULL;

    const int nk = K >> 4;
    const int ac  = (tid & 3) << 2;
    const int arB = tid >> 2;
    const int bcc = (tid & 31) << 2;
    const int brB = tid >> 5;

    float4 pa[2], pb[2];

    auto gload = [&](int kt) {
        #pragma unroll
        for (int p = 0; p < 2; p++) {
            int r = arB + p * 64;
            pa[p] = (row0 + r < Nrows)
                ? *(const float4*)(A + (size_t)(row0 + r) * K + kt * 16 + ac)
                : make_float4(0.f, 0.f, 0.f, 0.f);
        }
        #pragma unroll
        for (int p = 0; p < 2; p++) {
            int br = brB + p * 8;
            pb[p] = *(const float4*)(Bm + (size_t)(kt * 16 + br) * ncols + col0 + bcc);
        }
    };
    auto sstore = [&]() {
        #pragma unroll
        for (int p = 0; p < 2; p++) {
            int r = arB + p * 64;
            As[(ac + 0) * ASTR + r] = pa[p].x;
            As[(ac + 1) * ASTR + r] = pa[p].y;
            As[(ac + 2) * ASTR + r] = pa[p].z;
            As[(ac + 3) * ASTR + r] = pa[p].w;
        }
        #pragma unroll
        for (int p = 0; p < 2; p++) {
            int br = brB + p * 8;
            *(float4*)&Bs[br * 128 + bcc] = pb[p];
        }
    };

    gload(0); sstore();
    __syncthreads();

    for (int kt = 0; kt < nk; kt++) {
        if (kt + 1 < nk) gload(kt + 1);
        #pragma unroll
        for (int k = 0; k < 16; k++) {
            float4 a0 = *(const float4*)&As[k * ASTR + ty * 4];
            float4 a1 = *(const float4*)&As[k * ASTR + 64 + ty * 4];
            ulonglong2 b0 = *(const ulonglong2*)&Bs[k * 128 + tx * 4];
            ulonglong2 b1 = *(const ulonglong2*)&Bs[k * 128 + 64 + tx * 4];
            u64 bp[4] = {b0.x, b0.y, b1.x, b1.y};
            float av[8] = {a0.x, a0.y, a0.z, a0.w, a1.x, a1.y, a1.z, a1.w};
            #pragma unroll
            for (int i = 0; i < 8; i++) {
                u64 ad = dup2(av[i]);
                #pragma unroll
                for (int j = 0; j < 4; j++)
                    ffma2(acc2[i][j], ad, bp[j]);
            }
        }
        if (kt + 1 < nk) {
            __syncthreads();
            sstore();
            __syncthreads();
        }
    }
}

#define EPI_ROW(i)  (row0 + ((i) < 4 ? ty * 4 + (i) : 64 + ty * 4 + (i) - 4))
#define EPI_COL0    (col0 + tx * 4)
#define EPI_COL1    (col0 + 64 + tx * 4)

// GEMMW: Wc = W_r2 @ W_mu
__global__ void __launch_bounds__(256) k_gemmW(
    const float* __restrict__ Wr2, const float* __restrict__ Wmu)
{
    u64 acc2[8][4];
    sgemm_body(Wr2, Wmu, D2HC, DHC, DHC, acc2);
    const int ty = threadIdx.x >> 4, tx = threadIdx.x & 15;
    const int row0 = blockIdx.y * 128, col0 = blockIdx.x * 128;
    #pragma unroll
    for (int i = 0; i < 8; i++) {
        int r = EPI_ROW(i);
        float2 c0 = unpk(acc2[i][0]), c1 = unpk(acc2[i][1]);
        float2 c2 = unpk(acc2[i][2]), c3 = unpk(acc2[i][3]);
        *(float4*)(d_wc + (size_t)r * DHC + EPI_COL0) = make_float4(c0.x, c0.y, c1.x, c1.y);
        *(float4*)(d_wc + (size_t)r * DHC + EPI_COL1) = make_float4(c2.x, c2.y, c3.x, c3.y);
    }
}

// GEMM1: mh = h @ W_mu (stored raw); z_h = mh*(1-t) + sig*eps_h
__global__ void __launch_bounds__(256) k_gemm1(
    const float* __restrict__ h, const float* __restrict__ Wmu,
    const float* __restrict__ eh, const int* __restrict__ idx, int N)
{
    u64 acc2[8][4];
    sgemm_body(h, Wmu, N, DHC, DHC, acc2);
    const int ty = threadIdx.x >> 4, tx = threadIdx.x & 15;
    const int row0 = blockIdx.y * 128, col0 = blockIdx.x * 128;
    #pragma unroll
    for (int i = 0; i < 8; i++) {
        int r = EPI_ROW(i);
        if (r >= N) continue;
        int b = idx[r];
        float omt = d_gpar[b*GS+1], sig = d_gpar[b*GS+2];
        float2 c0 = unpk(acc2[i][0]), c1 = unpk(acc2[i][1]);
        float2 c2 = unpk(acc2[i][2]), c3 = unpk(acc2[i][3]);
        float4 m0 = make_float4(c0.x, c0.y, c1.x, c1.y);
        float4 m1 = make_float4(c2.x, c2.y, c3.x, c3.y);
        *(float4*)(d_mh + (size_t)r * DHC + EPI_COL0) = m0;
        *(float4*)(d_mh + (size_t)r * DHC + EPI_COL1) = m1;
        float4 e0 = *(const float4*)(eh + (size_t)r * DHC + EPI_COL0);
        float4 e1 = *(const float4*)(eh + (size_t)r * DHC + EPI_COL1);
        float4 o0, o1;
        o0.x = m0.x*omt + sig*e0.x; o0.y = m0.y*omt + sig*e0.y;
        o0.z = m0.z*omt + sig*e0.z; o0.w = m0.w*omt + sig*e0.w;
        o1.x = m1.x*omt + sig*e1.x; o1.y = m1.y*omt + sig*e1.y;
        o1.z = m1.z*omt + sig*e1.z; o1.w = m1.w*omt + sig*e1.w;
        *(float4*)(d_zh + (size_t)r * DHC + EPI_COL0) = o0;
        *(float4*)(d_zh + (size_t)r * DHC + EPI_COL1) = o1;
    }
}

// GEMM2: a1 = tanh(z_h @ W_r1)
__global__ void __launch_bounds__(256) k_gemm2(
    const float* __restrict__ Wr1, int N)
{
    u64 acc2[8][4];
    sgemm_body(d_zh, Wr1, N, DHC, D2HC, acc2);
    const int ty = threadIdx.x >> 4, tx = threadIdx.x & 15;
    const int row0 = blockIdx.y * 128, col0 = blockIdx.x * 128;
    #pragma unroll
    for (int i = 0; i < 8; i++) {
        int r = EPI_ROW(i);
        if (r >= N) continue;
        float2 c0 = unpk(acc2[i][0]), c1 = unpk(acc2[i][1]);
        float2 c2 = unpk(acc2[i][2]), c3 = unpk(acc2[i][3]);
        float4 o0, o1;
        o0.x = tanhf(c0.x); o0.y = tanhf(c0.y);
        o0.z = tanhf(c1.x); o0.w = tanhf(c1.y);
        o1.x = tanhf(c2.x); o1.y = tanhf(c2.y);
        o1.z = tanhf(c3.x); o1.w = tanhf(c3.y);
        *(float4*)(d_a1 + (size_t)r * D2HC + EPI_COL0) = o0;
        *(float4*)(d_a1 + (size_t)r * D2HC + EPI_COL1) = o1;
    }
}

// GEMM34: E = a1 @ Wc; loss += sum(s^2 * (mh - E)^2)
__global__ void __launch_bounds__(256) k_gemm34(
    const int* __restrict__ idx, int N)
{
    u64 acc2[8][4];
    sgemm_body(d_a1, d_wc, N, D2HC, DHC, acc2);
    const int ty = threadIdx.x >> 4, tx = threadIdx.x & 15;
    const int row0 = blockIdx.y * 128, col0 = blockIdx.x * 128;
    float local = 0.f;
    #pragma unroll
    for (int i = 0; i < 8; i++) {
        int r = EPI_ROW(i);
        if (r >= N) continue;
        int b = idx[r];
        float s = d_gpar[b*GS+8];
        float2 c0 = unpk(acc2[i][0]), c1 = unpk(acc2[i][1]);
        float2 c2 = unpk(acc2[i][2]), c3 = unpk(acc2[i][3]);
        float4 m0 = *(const float4*)(d_mh + (size_t)r * DHC + EPI_COL0);
        float4 m1 = *(const float4*)(d_mh + (size_t)r * DHC + EPI_COL1);
        float v0 = m0.x - c0.x, v1 = m0.y - c0.y, v2 = m0.z - c1.x, v3 = m0.w - c1.y;
        float v4 = m1.x - c2.x, v5 = m1.y - c2.y, v6 = m1.z - c3.x, v7 = m1.w - c3.y;
        float rs = v0*v0 + v1*v1 + v2*v2 + v3*v3 + v4*v4 + v5*v5 + v6*v6 + v7*v7;
        local += s * s * rs;
    }
    __shared__ float red[256];
    __syncthreads();
    red[threadIdx.x] = local;
    __syncthreads();
    for (int off = 128; off > 0; off >>= 1) {
        if (threadIdx.x < off) red[threadIdx.x] += red[threadIdx.x + off];
        __syncthreads();
    }
    if (threadIdx.x == 0) atomicAdd(&d_lossH, (double)red[0]);
}

// ---------------- small helpers / setup ----------------
__device__ __forceinline__ float softplusf(float x) {
    return fmaxf(x, 0.f) + log1pf(expf(-fabsf(x)));
}
__device__ __forceinline__ void syminv3(const float s[6], float o[6]) {
    float s00=s[0], s01=s[1], s02=s[2], s11=s[3], s12=s[4], s22=s[5];
    float det = s00*(s11*s22 - s12*s12) - s01*(s01*s22 - s12*s02) + s02*(s01*s12 - s11*s02);
    float id = 1.f / det;
    o[0] = (s11*s22 - s12*s12)*id;
    o[1] = (s02*s12 - s01*s22)*id;
    o[2] = (s01*s12 - s02*s11)*id;
    o[3] = (s00*s22 - s02*s02)*id;
    o[4] = (s01*s02 - s00*s12)*id;
    o[5] = (s00*s11 - s01*s01)*id;
}
__device__ __forceinline__ void symmv(const float m[6], const float v[3], float o[3]) {
    o[0] = m[0]*v[0] + m[1]*v[1] + m[2]*v[2];
    o[1] = m[1]*v[0] + m[3]*v[1] + m[4]*v[2];
    o[2] = m[2]*v[0] + m[4]*v[1] + m[5]*v[2];
}

__global__ void k_scalars(const float* __restrict__ t,
                          const float* __restrict__ gph,
                          const float* __restrict__ gpp,
                          int B, int N) {
    int b = blockIdx.x * blockDim.x + threadIdx.x;
    if (b == 0) { d_start[B] = N; d_lossH = 0.0; d_lossP = 0.0; }
    if (b >= B) return;
    float tb  = t[b];
    float sph = softplusf(gph[0]);
    float spp = softplusf(gpp[0]);
    float gh  = 0.1f + sph * tb;
    float gp  = 0.1f + spp * tb;
    float sig = 0.1f + 0.9f * tb;
    float omt = 1.f - tb;
    float a   = 0.2f + 0.8f * tb;
    float bb  = 0.1f * tb;
    float s   = (1.f + (0.9f + 0.5f*gh*gh/sig) * omt / sig) / gh;
    float* g = &d_gpar[b * GS];
    g[0]=tb; g[1]=omt; g[2]=sig; g[3]=a; g[4]=bb; g[5]=1.f/a;
    g[6]=gp; g[7]=0.5f*gp*gp; g[8]=s;
}

__global__ void k_starts(const int* __restrict__ idx, int N) {
    int n = blockIdx.x * blockDim.x + threadIdx.x;
    if (n >= N) return;
    int b = idx[n];
    if (n == 0 || idx[n-1] != b) d_start[b] = n;
}

// ---------------- FUSED pos branch: one block (64 thr) per graph ----------
// All 4 passes + the 3 per-graph "fin" steps run in one kernel; per-graph
// reductions and scalars live in shared memory.
__global__ void __launch_bounds__(64) k_pos(
    const float* __restrict__ pos, const float* __restrict__ ep)
{
    __shared__ float sh[15][64];
    __shared__ float P[24];   // fin scratch

    const int b = blockIdx.x, tid = threadIdx.x;
    const int s0 = d_start[b], s1 = d_start[b+1];
    const float cnt = (float)(s1 - s0);
    const float* G = &d_gpar[b*GS];
    const float omt = G[1], sig = G[2], a = G[3], bb = G[4], alpha = G[5];
    const float gp = G[6], gph2 = G[7];

    // helper lambda-free macro-ish reduction
    auto reduce = [&](float* acc, int nc) {
        for (int c = 0; c < nc; c++) sh[c][tid] = acc[c];
        __syncthreads();
        for (int off = 32; off > 0; off >>= 1) {
            if (tid < off)
                for (int c = 0; c < nc; c++) sh[c][tid] += sh[c][tid + off];
            __syncthreads();
        }
    };

    // ---- PASS A ----
    {
        float acc[15];
        #pragma unroll
        for (int c = 0; c < 15; c++) acc[c] = 0.f;
        for (int n = s0 + tid; n < s1; n += 64) {
            float p0 = pos[3*n], p1 = pos[3*n+1], p2 = pos[3*n+2];
            float e0 = ep[3*n],  e1 = ep[3*n+1],  e2 = ep[3*n+2];
            float pn = sqrtf(p0*p0 + p1*p1 + p2*p2);
            float iv = 1.f / (pn + EPSV);
            float n0 = p0*iv, n1 = p1*iv, n2 = p2*iv;
            float nn = n0*n0 + n1*n1 + n2*n2;
            float beta = -bb / (a * (a + bb * nn));
            float nde = n0*e0 + n1*e1 + n2*e2;
            acc[0] += beta*n0*n0; acc[1] += beta*n0*n1; acc[2] += beta*n0*n2;
            acc[3] += beta*n1*n1; acc[4] += beta*n1*n2; acc[5] += beta*n2*n2;
            acc[6]  += alpha*e0 + beta*nde*n0;
            acc[7]  += alpha*e1 + beta*nde*n1;
            acc[8]  += alpha*e2 + beta*nde*n2;
            acc[9]  += a*e0 + bb*nde*n0;
            acc[10] += a*e1 + bb*nde*n1;
            acc[11] += a*e2 + bb*nde*n2;
            acc[12] += 0.8f*e0 + 0.1f*nde*n0;
            acc[13] += 0.8f*e1 + 0.1f*nde*n1;
            acc[14] += 0.8f*e2 + 0.1f*nde*n2;
        }
        reduce(acc, 15);
        if (tid == 0) {
            float S[6] = {sh[0][0] + cnt*alpha, sh[1][0], sh[2][0],
                          sh[3][0] + cnt*alpha, sh[4][0], sh[5][0] + cnt*alpha};
            float iV[6]; syminv3(S, iV);
            float yb[3] = {sh[6][0], sh[7][0], sh[8][0]};
            float w[3];  symmv(iV, yb, w);
            P[0]=w[0]; P[1]=w[1]; P[2]=w[2];
            P[3]=sh[9][0]/cnt;  P[4]=sh[10][0]/cnt; P[5]=sh[11][0]/cnt;
            P[6]=sh[12][0]/cnt; P[7]=sh[13][0]/cnt; P[8]=sh[14][0]/cnt;
        }
        __syncthreads();
    }

    // ---- PASS B ----
    {
        const float w0=P[0], w1=P[1], w2_=P[2];
        const float mUe0=P[3], mUe1=P[4], mUe2=P[5];
        const float mdU0=P[6], mdU1=P[7], mdU2=P[8];
        float acc[9];
        #pragma unroll
        for (int c = 0; c < 9; c++) acc[c] = 0.f;
        for (int n = s0 + tid; n < s1; n += 64) {
            float p0 = pos[3*n], p1 = pos[3*n+1], p2 = pos[3*n+2];
            float e0 = ep[3*n],  e1 = ep[3*n+1],  e2 = ep[3*n+2];
            float pn = sqrtf(p0*p0 + p1*p1 + p2*p2);
            float iv = 1.f / (pn + EPSV);
            float n0 = p0*iv, n1 = p1*iv, n2 = p2*iv;
            float nn = n0*n0 + n1*n1 + n2*n2;
            float beta = -bb / (a * (a + bb * nn));
            float nde = n0*e0 + n1*e1 + n2*e2;
            float y0 = alpha*e0 + beta*nde*n0, y1 = alpha*e1 + beta*nde*n1, y2 = alpha*e2 + beta*nde*n2;
            float Ue0 = a*e0 + bb*nde*n0, Ue1 = a*e1 + bb*nde*n1, Ue2 = a*e2 + bb*nde*n2;
            float dU0 = 0.8f*e0 + 0.1f*nde*n0, dU1 = 0.8f*e1 + 0.1f*nde*n1, dU2v = 0.8f*e2 + 0.1f*nde*n2;
            float zp0 = omt*p0 + Ue0 - mUe0;
            float zp1 = omt*p1 + Ue1 - mUe1;
            float zp2 = omt*p2 + Ue2 - mUe2;
            d_zp[3*n]=zp0; d_zp[3*n+1]=zp1; d_zp[3*n+2]=zp2;
            float ndw = n0*w0 + n1*w1 + n2*w2_;
            float iw0 = alpha*w0 + beta*ndw*n0, iw1 = alpha*w1 + beta*ndw*n1, iw2 = alpha*w2_ + beta*ndw*n2;
            d_tgtp[3*n]   = -p0 + dU0  - mdU0 - gph2*(iw0 - y0);
            d_tgtp[3*n+1] = -p1 + dU1  - mdU1 - gph2*(iw1 - y1);
            d_tgtp[3*n+2] = -p2 + dU2v - mdU2 - gph2*(iw2 - y2);
            float pr0 = 0.9f*zp0, pr1 = 0.9f*zp1, pr2 = 0.9f*zp2;
            float rl0 = sig*zp0,  rl1 = sig*zp1,  rl2 = sig*zp2;
            float prn = sqrtf(pr0*pr0 + pr1*pr1 + pr2*pr2);
            float iv2 = 1.f / (prn + EPSV);
            float m0 = pr0*iv2, m1 = pr1*iv2, m2 = pr2*iv2;
            float mm = m0*m0 + m1*m1 + m2*m2;
            float beta2 = -bb / (a * (a + bb * mm));
            float ndp = m0*rl0 + m1*rl1 + m2*rl2;
            acc[0] += beta2*m0*m0; acc[1] += beta2*m0*m1; acc[2] += beta2*m0*m2;
            acc[3] += beta2*m1*m1; acc[4] += beta2*m1*m2; acc[5] += beta2*m2*m2;
            acc[6] += (alpha - 1.f)*rl0 + beta2*ndp*m0;
            acc[7] += (alpha - 1.f)*rl1 + beta2*ndp*m1;
            acc[8] += (alpha - 1.f)*rl2 + beta2*ndp*m2;
        }
        __syncthreads();   // protect sh reuse
        reduce(acc, 9);
        if (tid == 0) {
            float S[6] = {sh[0][0] + cnt*alpha, sh[1][0], sh[2][0],
                          sh[3][0] + cnt*alpha, sh[4][0], sh[5][0] + cnt*alpha};
            float iV[6]; syminv3(S, iV);
            float q[3] = {sh[6][0], sh[7][0], sh[8][0]};
            float c[3]; symmv(iV, q, c);
            P[9]=iV[0]; P[10]=iV[1]; P[11]=iV[2]; P[12]=iV[3]; P[13]=iV[4]; P[14]=iV[5];
            P[15]=c[0]; P[16]=c[1];  P[17]=c[2];
        }
        __syncthreads();
    }

    // ---- PASS C ----
    {
        const float c0 = P[15], c1 = P[16], c2 = P[17];
        float acc[6];
        #pragma unroll
        for (int c = 0; c < 6; c++) acc[c] = 0.f;
        for (int n = s0 + tid; n < s1; n += 64) {
            float zp0 = d_zp[3*n], zp1 = d_zp[3*n+1], zp2 = d_zp[3*n+2];
            float pr0 = 0.9f*zp0, pr1 = 0.9f*zp1, pr2 = 0.9f*zp2;
            float prn = sqrtf(pr0*pr0 + pr1*pr1 + pr2*pr2);
            float iv = 1.f / (prn + EPSV);
            float m0 = pr0*iv, m1 = pr1*iv, m2 = pr2*iv;
            float mm = m0*m0 + m1*m1 + m2*m2;
            float beta2 = -bb / (a * (a + bb * mm));
            float v0 = sig*zp0 - c0, v1 = sig*zp1 - c1, v2 = sig*zp2 - c2;
            float ndv = m0*v0 + m1*v1 + m2*v2;
            float e0 = alpha*v0 + beta2*ndv*m0;
            float e1 = alpha*v1 + beta2*ndv*m1;
            float e2 = alpha*v2 + beta2*ndv*m2;
            d_eps2[3*n]=e0; d_eps2[3*n+1]=e1; d_eps2[3*n+2]=e2;
            float nde = m0*e0 + m1*e1 + m2*e2;
            acc[0] += alpha*e0 + beta2*nde*m0;
            acc[1] += alpha*e1 + beta2*nde*m1;
            acc[2] += alpha*e2 + beta2*nde*m2;
            acc[3] += 0.8f*e0 + 0.1f*nde*m0;
            acc[4] += 0.8f*e1 + 0.1f*nde*m1;
            acc[5] += 0.8f*e2 + 0.1f*nde*m2;
        }
        __syncthreads();
        reduce(acc, 6);
        if (tid == 0) {
            float iV[6] = {P[9], P[10], P[11], P[12], P[13], P[14]};
            float yb[3] = {sh[0][0], sh[1][0], sh[2][0]};
            float w2[3]; symmv(iV, yb, w2);
            P[18]=w2[0]; P[19]=w2[1]; P[20]=w2[2];
            P[21]=sh[3][0]/cnt; P[22]=sh[4][0]/cnt; P[23]=sh[5][0]/cnt;
        }
        __syncthreads();
    }

    // ---- PASS D ----
    {
        const float w0=P[18], w1=P[19], w2_=P[20];
        const float md0=P[21], md1=P[22], md2=P[23];
        const float igp = 1.f / gp;
        float local = 0.f;
        for (int n = s0 + tid; n < s1; n += 64) {
            float zp0 = d_zp[3*n], zp1 = d_zp[3*n+1], zp2 = d_zp[3*n+2];
            float e0 = d_eps2[3*n], e1 = d_eps2[3*n+1], e2 = d_eps2[3*n+2];
            float pr0 = 0.9f*zp0, pr1 = 0.9f*zp1, pr2 = 0.9f*zp2;
            float prn = sqrtf(pr0*pr0 + pr1*pr1 + pr2*pr2);
            float iv = 1.f / (prn + EPSV);
            float m0 = pr0*iv, m1 = pr1*iv, m2 = pr2*iv;
            float mm = m0*m0 + m1*m1 + m2*m2;
            float beta2 = -bb / (a * (a + bb * mm));
            float nde = m0*e0 + m1*e1 + m2*e2;
            float y0 = alpha*e0 + beta2*nde*m0, y1 = alpha*e1 + beta2*nde*m1, y2 = alpha*e2 + beta2*nde*m2;
            float du0 = 0.8f*e0 + 0.1f*nde*m0, du1 = 0.8f*e1 + 0.1f*nde*m1, du2 = 0.8f*e2 + 0.1f*nde*m2;
            float ndw = m0*w0 + m1*w1 + m2*w2_;
            float iw0 = alpha*w0 + beta2*ndw*m0, iw1 = alpha*w1 + beta2*ndw*m1, iw2 = alpha*w2_ + beta2*ndw*m2;
            float a0 = -pr0 + du0 - md0 - gph2*(iw0 - y0);
            float a1v = -pr1 + du1 - md1 - gph2*(iw1 - y1);
            float a2 = -pr2 + du2 - md2 - gph2*(iw2 - y2);
            float f0 = (a0  - d_tgtp[3*n])   * igp;
            float f1 = (a1v - d_tgtp[3*n+1]) * igp;
            float f2 = (a2  - d_tgtp[3*n+2]) * igp;
            local += f0*f0 + f1*f1 + f2*f2;
        }
        __syncthreads();
        float acc[1] = {local};
        reduce(acc, 1);
        if (tid == 0) atomicAdd(&d_lossP, (double)sh[0][0]);
    }
}

__global__ void k_final(float* out, int N) {
    out[0] = (float)(d_lossH / ((double)N * 256.0));
    out[1] = (float)(d_lossP / ((double)N * 3.0));
}

// ---------------- launch ----------------
extern "C" void kernel_launch(void* const* d_in, const int* in_sizes, int n_in,
                              void* d_out, int out_size) {
    const float* t      = (const float*)d_in[0];
    const float* h      = (const float*)d_in[1];
    const float* pos    = (const float*)d_in[2];
    const float* eps_h  = (const float*)d_in[3];
    const float* eps_p  = (const float*)d_in[4];
    const float* gph    = (const float*)d_in[5];
    const float* gpp    = (const float*)d_in[6];
    const float* W_mu   = (const float*)d_in[7];
    const float* W_r1   = (const float*)d_in[8];
    const float* W_r2   = (const float*)d_in[9];
    const int*   idx    = (const int*)d_in[10];

    int B = in_sizes[0];
    int N = in_sizes[10];
    float* out = (float*)d_out;

    k_scalars<<<(B + 255) / 256, 256>>>(t, gph, gpp, B, N);
    k_starts<<<(N + 255) / 256, 256>>>(idx, N);

    k_gemmW<<<dim3(2, 4), 256>>>(W_r2, W_mu);

    int mt = (N + 127) / 128;
    k_gemm1<<<dim3(2, mt), 256>>>(h, W_mu, eps_h, idx, N);
    k_gemm2<<<dim3(4, mt), 256>>>(W_r1, N);
    k_gemm34<<<dim3(2, mt), 256>>>(idx, N);

    k_pos<<<B, 64>>>(pos, eps_p);

    k_final<<<1, 1>>>(out, N);
}

// round 13
// speedup vs baseline: 1.1109x; 1.0186x over previous
#include <cuda_runtime.h>
#include <math.h>
#include <stdint.h>

#define MAXN 100352          // padded N (N = 100000)
#define BMAX 2048
#define DHC  256
#define D2HC 512
#define EPSV 1e-6f
#define GS   16

typedef unsigned long long u64;

// ---------------- device scratch ----------------
__device__ float d_zh[MAXN * DHC];     // z_h
__device__ float d_mh[MAXN * DHC];     // mh = h @ W_mu (raw)
__device__ float d_a1[MAXN * D2HC];    // tanh(z_h @ W_r1)
__device__ float d_wc[D2HC * DHC];     // Wc = W_r2 @ W_mu
__device__ float d_zp[MAXN * 3];
__device__ float d_tgtp[MAXN * 3];
__device__ float d_eps2[MAXN * 3];

__device__ float d_gpar[BMAX * GS];
__device__ int   d_start[BMAX + 1];
__device__ double d_lossH, d_lossP;

// ---------------- packed f32x2 helpers ----------------
__device__ __forceinline__ void ffma2(u64 &d, u64 a, u64 b) {
    asm("fma.rn.f32x2 %0, %1, %2, %0;" : "+l"(d) : "l"(a), "l"(b));
}
__device__ __forceinline__ u64 dup2(float x) {
    u64 r;
    asm("mov.b64 %0, {%1, %1};" : "=l"(r) : "r"(__float_as_uint(x)));
    return r;
}
__device__ __forceinline__ float2 unpk(u64 v) {
    float2 f;
    asm("mov.b64 {%0, %1}, %2;" : "=f"(f.x), "=f"(f.y) : "l"(v));
    return f;
}

// ---------------- SGEMM core (R10 winner): 128x128, BK=16 ----------------
#define ASTR 132                 // padded A row stride (floats)
#define SMEM_FLOATS (16*ASTR + 16*128)   // 4160 floats = 16640 B

__device__ __forceinline__ void sgemm_body(
    float* smem,
    const float* __restrict__ A, const float* __restrict__ Bm,
    int Nrows, int K, int ncols, int row0, int col0, u64 acc2[8][4])
{
    float* As = smem;                // [k][m] padded
    float* Bs = smem + 16 * ASTR;    // [k][n]

    const int tid = threadIdx.x;
    const int ty = tid >> 4, tx = tid & 15;

    #pragma unroll
    for (int i = 0; i < 8; i++)
        #pragma unroll
        for (int j = 0; j < 4; j++) acc2[i][j] = 0ULL;

    const int nk = K >> 4;
    const int ac  = (tid & 3) << 2;
    const int arB = tid >> 2;
    const int bcc = (tid & 31) << 2;
    const int brB = tid >> 5;

    float4 pa[2], pb[2];

    auto gload = [&](int kt) {
        #pragma unroll
        for (int p = 0; p < 2; p++) {
            int r = arB + p * 64;
            pa[p] = (row0 + r < Nrows)
                ? *(const float4*)(A + (size_t)(row0 + r) * K + kt * 16 + ac)
                : make_float4(0.f, 0.f, 0.f, 0.f);
        }
        #pragma unroll
        for (int p = 0; p < 2; p++) {
            int br = brB + p * 8;
            pb[p] = *(const float4*)(Bm + (size_t)(kt * 16 + br) * ncols + col0 + bcc);
        }
    };
    auto sstore = [&]() {
        #pragma unroll
        for (int p = 0; p < 2; p++) {
            int r = arB + p * 64;
            As[(ac + 0) * ASTR + r] = pa[p].x;
            As[(ac + 1) * ASTR + r] = pa[p].y;
            As[(ac + 2) * ASTR + r] = pa[p].z;
            As[(ac + 3) * ASTR + r] = pa[p].w;
        }
        #pragma unroll
        for (int p = 0; p < 2; p++) {
            int br = brB + p * 8;
            *(float4*)&Bs[br * 128 + bcc] = pb[p];
        }
    };

    gload(0); sstore();
    __syncthreads();

    for (int kt = 0; kt < nk; kt++) {
        if (kt + 1 < nk) gload(kt + 1);
        #pragma unroll
        for (int k = 0; k < 16; k++) {
            float4 a0 = *(const float4*)&As[k * ASTR + ty * 4];
            float4 a1 = *(const float4*)&As[k * ASTR + 64 + ty * 4];
            ulonglong2 b0 = *(const ulonglong2*)&Bs[k * 128 + tx * 4];
            ulonglong2 b1 = *(const ulonglong2*)&Bs[k * 128 + 64 + tx * 4];
            u64 bp[4] = {b0.x, b0.y, b1.x, b1.y};
            float av[8] = {a0.x, a0.y, a0.z, a0.w, a1.x, a1.y, a1.z, a1.w};
            #pragma unroll
            for (int i = 0; i < 8; i++) {
                u64 ad = dup2(av[i]);
                #pragma unroll
                for (int j = 0; j < 4; j++)
                    ffma2(acc2[i][j], ad, bp[j]);
            }
        }
        if (kt + 1 < nk) {
            __syncthreads();
            sstore();
            __syncthreads();
        }
    }
}

#define EPI_ROW(i)  (row0 + ((i) < 4 ? ty * 4 + (i) : 64 + ty * 4 + (i) - 4))
#define EPI_COL0    (col0 + tx * 4)
#define EPI_COL1    (col0 + 64 + tx * 4)

// ---------------- small helpers ----------------
__device__ __forceinline__ float softplusf(float x) {
    return fmaxf(x, 0.f) + log1pf(expf(-fabsf(x)));
}
__device__ __forceinline__ void syminv3(const float s[6], float o[6]) {
    float s00=s[0], s01=s[1], s02=s[2], s11=s[3], s12=s[4], s22=s[5];
    float det = s00*(s11*s22 - s12*s12) - s01*(s01*s22 - s12*s02) + s02*(s01*s12 - s11*s02);
    float id = 1.f / det;
    o[0] = (s11*s22 - s12*s12)*id;
    o[1] = (s02*s12 - s01*s22)*id;
    o[2] = (s01*s12 - s02*s11)*id;
    o[3] = (s00*s22 - s02*s02)*id;
    o[4] = (s01*s02 - s00*s12)*id;
    o[5] = (s00*s11 - s01*s01)*id;
}
__device__ __forceinline__ void symmv(const float m[6], const float v[3], float o[3]) {
    o[0] = m[0]*v[0] + m[1]*v[1] + m[2]*v[2];
    o[1] = m[1]*v[0] + m[3]*v[1] + m[4]*v[2];
    o[2] = m[2]*v[0] + m[4]*v[1] + m[5]*v[2];
}

// ---------------- pos branch body (256 threads per block) ----------------
__device__ void pos_block(float* smem, int b,
                          const float* __restrict__ pos, const float* __restrict__ ep)
{
    float* sh = smem;            // 15*256 floats
    float* P  = smem + 15*256;   // 24 floats fin scratch

    const int tid = threadIdx.x;
    const int s0 = d_start[b], s1 = d_start[b+1];
    const float cnt = (float)(s1 - s0);
    const float* G = &d_gpar[b*GS];
    const float omt = G[1], sig = G[2], a = G[3], bb = G[4], alpha = G[5];
    const float gp = G[6], gph2 = G[7];

    auto reduce = [&](float* acc, int nc) {
        for (int c = 0; c < nc; c++) sh[c*256 + tid] = acc[c];
        __syncthreads();
        for (int off = 128; off > 0; off >>= 1) {
            if (tid < off)
                for (int c = 0; c < nc; c++) sh[c*256 + tid] += sh[c*256 + tid + off];
            __syncthreads();
        }
    };

    // ---- PASS A ----
    {
        float acc[15];
        #pragma unroll
        for (int c = 0; c < 15; c++) acc[c] = 0.f;
        for (int n = s0 + tid; n < s1; n += 256) {
            float p0 = pos[3*n], p1 = pos[3*n+1], p2 = pos[3*n+2];
            float e0 = ep[3*n],  e1 = ep[3*n+1],  e2 = ep[3*n+2];
            float pn = sqrtf(p0*p0 + p1*p1 + p2*p2);
            float iv = 1.f / (pn + EPSV);
            float n0 = p0*iv, n1 = p1*iv, n2 = p2*iv;
            float nn = n0*n0 + n1*n1 + n2*n2;
            float beta = -bb / (a * (a + bb * nn));
            float nde = n0*e0 + n1*e1 + n2*e2;
            acc[0] += beta*n0*n0; acc[1] += beta*n0*n1; acc[2] += beta*n0*n2;
            acc[3] += beta*n1*n1; acc[4] += beta*n1*n2; acc[5] += beta*n2*n2;
            acc[6]  += alpha*e0 + beta*nde*n0;
            acc[7]  += alpha*e1 + beta*nde*n1;
            acc[8]  += alpha*e2 + beta*nde*n2;
            acc[9]  += a*e0 + bb*nde*n0;
            acc[10] += a*e1 + bb*nde*n1;
            acc[11] += a*e2 + bb*nde*n2;
            acc[12] += 0.8f*e0 + 0.1f*nde*n0;
            acc[13] += 0.8f*e1 + 0.1f*nde*n1;
            acc[14] += 0.8f*e2 + 0.1f*nde*n2;
        }
        reduce(acc, 15);
        if (tid == 0) {
            float S[6] = {sh[0*256] + cnt*alpha, sh[1*256], sh[2*256],
                          sh[3*256] + cnt*alpha, sh[4*256], sh[5*256] + cnt*alpha};
            float iV[6]; syminv3(S, iV);
            float yb[3] = {sh[6*256], sh[7*256], sh[8*256]};
            float w[3];  symmv(iV, yb, w);
            P[0]=w[0]; P[1]=w[1]; P[2]=w[2];
            P[3]=sh[9*256]/cnt;  P[4]=sh[10*256]/cnt; P[5]=sh[11*256]/cnt;
            P[6]=sh[12*256]/cnt; P[7]=sh[13*256]/cnt; P[8]=sh[14*256]/cnt;
        }
        __syncthreads();
    }

    // ---- PASS B ----
    {
        const float w0=P[0], w1=P[1], w2_=P[2];
        const float mUe0=P[3], mUe1=P[4], mUe2=P[5];
        const float mdU0=P[6], mdU1=P[7], mdU2=P[8];
        float acc[9];
        #pragma unroll
        for (int c = 0; c < 9; c++) acc[c] = 0.f;
        for (int n = s0 + tid; n < s1; n += 256) {
            float p0 = pos[3*n], p1 = pos[3*n+1], p2 = pos[3*n+2];
            float e0 = ep[3*n],  e1 = ep[3*n+1],  e2 = ep[3*n+2];
            float pn = sqrtf(p0*p0 + p1*p1 + p2*p2);
            float iv = 1.f / (pn + EPSV);
            float n0 = p0*iv, n1 = p1*iv, n2 = p2*iv;
            float nn = n0*n0 + n1*n1 + n2*n2;
            float beta = -bb / (a * (a + bb * nn));
            float nde = n0*e0 + n1*e1 + n2*e2;
            float y0 = alpha*e0 + beta*nde*n0, y1 = alpha*e1 + beta*nde*n1, y2 = alpha*e2 + beta*nde*n2;
            float Ue0 = a*e0 + bb*nde*n0, Ue1 = a*e1 + bb*nde*n1, Ue2 = a*e2 + bb*nde*n2;
            float dU0 = 0.8f*e0 + 0.1f*nde*n0, dU1 = 0.8f*e1 + 0.1f*nde*n1, dU2v = 0.8f*e2 + 0.1f*nde*n2;
            float zp0 = omt*p0 + Ue0 - mUe0;
            float zp1 = omt*p1 + Ue1 - mUe1;
            float zp2 = omt*p2 + Ue2 - mUe2;
            d_zp[3*n]=zp0; d_zp[3*n+1]=zp1; d_zp[3*n+2]=zp2;
            float ndw = n0*w0 + n1*w1 + n2*w2_;
            float iw0 = alpha*w0 + beta*ndw*n0, iw1 = alpha*w1 + beta*ndw*n1, iw2 = alpha*w2_ + beta*ndw*n2;
            d_tgtp[3*n]   = -p0 + dU0  - mdU0 - gph2*(iw0 - y0);
            d_tgtp[3*n+1] = -p1 + dU1  - mdU1 - gph2*(iw1 - y1);
            d_tgtp[3*n+2] = -p2 + dU2v - mdU2 - gph2*(iw2 - y2);
            float pr0 = 0.9f*zp0, pr1 = 0.9f*zp1, pr2 = 0.9f*zp2;
            float rl0 = sig*zp0,  rl1 = sig*zp1,  rl2 = sig*zp2;
            float prn = sqrtf(pr0*pr0 + pr1*pr1 + pr2*pr2);
            float iv2 = 1.f / (prn + EPSV);
            float m0 = pr0*iv2, m1 = pr1*iv2, m2 = pr2*iv2;
            float mm = m0*m0 + m1*m1 + m2*m2;
            float beta2 = -bb / (a * (a + bb * mm));
            float ndp = m0*rl0 + m1*rl1 + m2*rl2;
            acc[0] += beta2*m0*m0; acc[1] += beta2*m0*m1; acc[2] += beta2*m0*m2;
            acc[3] += beta2*m1*m1; acc[4] += beta2*m1*m2; acc[5] += beta2*m2*m2;
            acc[6] += (alpha - 1.f)*rl0 + beta2*ndp*m0;
            acc[7] += (alpha - 1.f)*rl1 + beta2*ndp*m1;
            acc[8] += (alpha - 1.f)*rl2 + beta2*ndp*m2;
        }
        __syncthreads();
        reduce(acc, 9);
        if (tid == 0) {
            float S[6] = {sh[0*256] + cnt*alpha, sh[1*256], sh[2*256],
                          sh[3*256] + cnt*alpha, sh[4*256], sh[5*256] + cnt*alpha};
            float iV[6]; syminv3(S, iV);
            float q[3] = {sh[6*256], sh[7*256], sh[8*256]};
            float c[3]; symmv(iV, q, c);
            P[9]=iV[0]; P[10]=iV[1]; P[11]=iV[2]; P[12]=iV[3]; P[13]=iV[4]; P[14]=iV[5];
            P[15]=c[0]; P[16]=c[1];  P[17]=c[2];
        }
        __syncthreads();
    }

    // ---- PASS C ----
    {
        const float c0 = P[15], c1 = P[16], c2 = P[17];
        float acc[6];
        #pragma unroll
        for (int c = 0; c < 6; c++) acc[c] = 0.f;
        for (int n = s0 + tid; n < s1; n += 256) {
            float zp0 = d_zp[3*n], zp1 = d_zp[3*n+1], zp2 = d_zp[3*n+2];
            float pr0 = 0.9f*zp0, pr1 = 0.9f*zp1, pr2 = 0.9f*zp2;
            float prn = sqrtf(pr0*pr0 + pr1*pr1 + pr2*pr2);
            float iv = 1.f / (prn + EPSV);
            float m0 = pr0*iv, m1 = pr1*iv, m2 = pr2*iv;
            float mm = m0*m0 + m1*m1 + m2*m2;
            float beta2 = -bb / (a * (a + bb * mm));
            float v0 = sig*zp0 - c0, v1 = sig*zp1 - c1, v2 = sig*zp2 - c2;
            float ndv = m0*v0 + m1*v1 + m2*v2;
            float e0 = alpha*v0 + beta2*ndv*m0;
            float e1 = alpha*v1 + beta2*ndv*m1;
            float e2 = alpha*v2 + beta2*ndv*m2;
            d_eps2[3*n]=e0; d_eps2[3*n+1]=e1; d_eps2[3*n+2]=e2;
            float nde = m0*e0 + m1*e1 + m2*e2;
            acc[0] += alpha*e0 + beta2*nde*m0;
            acc[1] += alpha*e1 + beta2*nde*m1;
            acc[2] += alpha*e2 + beta2*nde*m2;
            acc[3] += 0.8f*e0 + 0.1f*nde*m0;
            acc[4] += 0.8f*e1 + 0.1f*nde*m1;
            acc[5] += 0.8f*e2 + 0.1f*nde*m2;
        }
        __syncthreads();
        reduce(acc, 6);
        if (tid == 0) {
            float iV[6] = {P[9], P[10], P[11], P[12], P[13], P[14]};
            float yb[3] = {sh[0*256], sh[1*256], sh[2*256]};
            float w2[3]; symmv(iV, yb, w2);
            P[18]=w2[0]; P[19]=w2[1]; P[20]=w2[2];
            P[21]=sh[3*256]/cnt; P[22]=sh[4*256]/cnt; P[23]=sh[5*256]/cnt;
        }
        __syncthreads();
    }

    // ---- PASS D ----
    {
        const float w0=P[18], w1=P[19], w2_=P[20];
        const float md0=P[21], md1=P[22], md2=P[23];
        const float igp = 1.f / gp;
        float local = 0.f;
        for (int n = s0 + tid; n < s1; n += 256) {
            float zp0 = d_zp[3*n], zp1 = d_zp[3*n+1], zp2 = d_zp[3*n+2];
            float e0 = d_eps2[3*n], e1 = d_eps2[3*n+1], e2 = d_eps2[3*n+2];
            float pr0 = 0.9f*zp0, pr1 = 0.9f*zp1, pr2 = 0.9f*zp2;
            float prn = sqrtf(pr0*pr0 + pr1*pr1 + pr2*pr2);
            float iv = 1.f / (prn + EPSV);
            float m0 = pr0*iv, m1 = pr1*iv, m2 = pr2*iv;
            float mm = m0*m0 + m1*m1 + m2*m2;
            float beta2 = -bb / (a * (a + bb * mm));
            float nde = m0*e0 + m1*e1 + m2*e2;
            float y0 = alpha*e0 + beta2*nde*m0, y1 = alpha*e1 + beta2*nde*m1, y2 = alpha*e2 + beta2*nde*m2;
            float du0 = 0.8f*e0 + 0.1f*nde*m0, du1 = 0.8f*e1 + 0.1f*nde*m1, du2 = 0.8f*e2 + 0.1f*nde*m2;
            float ndw = m0*w0 + m1*w1 + m2*w2_;
            float iw0 = alpha*w0 + beta2*ndw*m0, iw1 = alpha*w1 + beta2*ndw*m1, iw2 = alpha*w2_ + beta2*ndw*m2;
            float a0 = -pr0 + du0 - md0 - gph2*(iw0 - y0);
            float a1v = -pr1 + du1 - md1 - gph2*(iw1 - y1);
            float a2 = -pr2 + du2 - md2 - gph2*(iw2 - y2);
            float f0 = (a0  - d_tgtp[3*n])   * igp;
            float f1 = (a1v - d_tgtp[3*n+1]) * igp;
            float f2 = (a2  - d_tgtp[3*n+2]) * igp;
            local += f0*f0 + f1*f1 + f2*f2;
        }
        __syncthreads();
        float acc[1] = {local};
        reduce(acc, 1);
        if (tid == 0) atomicAdd(&d_lossP, (double)sh[0]);
    }
}

// ---------------- fused launch 1: gemmW (8 blocks) + gemm1 + pos ----------
__global__ void __launch_bounds__(256) k_fused1(
    const float* __restrict__ h, const float* __restrict__ Wmu,
    const float* __restrict__ eh, const int* __restrict__ idx,
    const float* __restrict__ Wr2,
    const float* __restrict__ pos, const float* __restrict__ ep,
    int N, int mt)
{
    __shared__ __align__(16) float smem[SMEM_FLOATS];
    const int gid = blockIdx.x;
    const int ty = threadIdx.x >> 4, tx = threadIdx.x & 15;

    if (gid < 8) {
        // gemmW: Wc = W_r2 @ W_mu  (512x256 out; 4 row-blocks x 2 col-blocks)
        int col0 = (gid & 1) * 128, row0 = (gid >> 1) * 128;
        u64 acc2[8][4];
        sgemm_body(smem, Wr2, Wmu, D2HC, DHC, DHC, row0, col0, acc2);
        #pragma unroll
        for (int i = 0; i < 8; i++) {
            int r = EPI_ROW(i);
            float2 c0 = unpk(acc2[i][0]), c1 = unpk(acc2[i][1]);
            float2 c2 = unpk(acc2[i][2]), c3 = unpk(acc2[i][3]);
            *(float4*)(d_wc + (size_t)r * DHC + EPI_COL0) = make_float4(c0.x, c0.y, c1.x, c1.y);
            *(float4*)(d_wc + (size_t)r * DHC + EPI_COL1) = make_float4(c2.x, c2.y, c3.x, c3.y);
        }
    } else if (gid < 8 + 2 * mt) {
        // gemm1
        int g = gid - 8;
        int col0 = (g & 1) * 128, row0 = (g >> 1) * 128;
        u64 acc2[8][4];
        sgemm_body(smem, h, Wmu, N, DHC, DHC, row0, col0, acc2);
        #pragma unroll
        for (int i = 0; i < 8; i++) {
            int r = EPI_ROW(i);
            if (r >= N) continue;
            int b = idx[r];
            float omt = d_gpar[b*GS+1], sig = d_gpar[b*GS+2];
            float2 c0 = unpk(acc2[i][0]), c1 = unpk(acc2[i][1]);
            float2 c2 = unpk(acc2[i][2]), c3 = unpk(acc2[i][3]);
            float4 m0 = make_float4(c0.x, c0.y, c1.x, c1.y);
            float4 m1 = make_float4(c2.x, c2.y, c3.x, c3.y);
            *(float4*)(d_mh + (size_t)r * DHC + EPI_COL0) = m0;
            *(float4*)(d_mh + (size_t)r * DHC + EPI_COL1) = m1;
            float4 e0 = *(const float4*)(eh + (size_t)r * DHC + EPI_COL0);
            float4 e1 = *(const float4*)(eh + (size_t)r * DHC + EPI_COL1);
            float4 o0, o1;
            o0.x = m0.x*omt + sig*e0.x; o0.y = m0.y*omt + sig*e0.y;
            o0.z = m0.z*omt + sig*e0.z; o0.w = m0.w*omt + sig*e0.w;
            o1.x = m1.x*omt + sig*e1.x; o1.y = m1.y*omt + sig*e1.y;
            o1.z = m1.z*omt + sig*e1.z; o1.w = m1.w*omt + sig*e1.w;
            *(float4*)(d_zh + (size_t)r * DHC + EPI_COL0) = o0;
            *(float4*)(d_zh + (size_t)r * DHC + EPI_COL1) = o1;
        }
    } else {
        // pos branch: one block per graph
        int b = gid - 8 - 2 * mt;
        pos_block(smem, b, pos, ep);
    }
}

// GEMM2: a1 = tanh(z_h @ W_r1)
__global__ void __launch_bounds__(256) k_gemm2(
    const float* __restrict__ Wr1, int N)
{
    __shared__ __align__(16) float smem[SMEM_FLOATS];
    u64 acc2[8][4];
    int row0 = blockIdx.y * 128, col0 = blockIdx.x * 128;
    sgemm_body(smem, d_zh, Wr1, N, DHC, D2HC, row0, col0, acc2);
    const int ty = threadIdx.x >> 4, tx = threadIdx.x & 15;
    #pragma unroll
    for (int i = 0; i < 8; i++) {
        int r = EPI_ROW(i);
        if (r >= N) continue;
        float2 c0 = unpk(acc2[i][0]), c1 = unpk(acc2[i][1]);
        float2 c2 = unpk(acc2[i][2]), c3 = unpk(acc2[i][3]);
        float4 o0, o1;
        o0.x = tanhf(c0.x); o0.y = tanhf(c0.y);
        o0.z = tanhf(c1.x); o0.w = tanhf(c1.y);
        o1.x = tanhf(c2.x); o1.y = tanhf(c2.y);
        o1.z = tanhf(c3.x); o1.w = tanhf(c3.y);
        *(float4*)(d_a1 + (size_t)r * D2HC + EPI_COL0) = o0;
        *(float4*)(d_a1 + (size_t)r * D2HC + EPI_COL1) = o1;
    }
}

// GEMM34: E = a1 @ Wc; loss += sum(s^2 * (mh - E)^2)
__global__ void __launch_bounds__(256) k_gemm34(
    const int* __restrict__ idx, int N)
{
    __shared__ __align__(16) float smem[SMEM_FLOATS];
    u64 acc2[8][4];
    int row0 = blockIdx.y * 128, col0 = blockIdx.x * 128;
    sgemm_body(smem, d_a1, d_wc, N, D2HC, DHC, row0, col0, acc2);
    const int ty = threadIdx.x >> 4, tx = threadIdx.x & 15;
    float local = 0.f;
    #pragma unroll
    for (int i = 0; i < 8; i++) {
        int r = EPI_ROW(i);
        if (r >= N) continue;
        int b = idx[r];
        float s = d_gpar[b*GS+8];
        float2 c0 = unpk(acc2[i][0]), c1 = unpk(acc2[i][1]);
        float2 c2 = unpk(acc2[i][2]), c3 = unpk(acc2[i][3]);
        float4 m0 = *(const float4*)(d_mh + (size_t)r * DHC + EPI_COL0);
        float4 m1 = *(const float4*)(d_mh + (size_t)r * DHC + EPI_COL1);
        float v0 = m0.x - c0.x, v1 = m0.y - c0.y, v2 = m0.z - c1.x, v3 = m0.w - c1.y;
        float v4 = m1.x - c2.x, v5 = m1.y - c2.y, v6 = m1.z - c3.x, v7 = m1.w - c3.y;
        float rs = v0*v0 + v1*v1 + v2*v2 + v3*v3 + v4*v4 + v5*v5 + v6*v6 + v7*v7;
        local += s * s * rs;
    }
    __syncthreads();
    smem[threadIdx.x] = local;
    __syncthreads();
    for (int off = 128; off > 0; off >>= 1) {
        if (threadIdx.x < off) smem[threadIdx.x] += smem[threadIdx.x + off];
        __syncthreads();
    }
    if (threadIdx.x == 0) atomicAdd(&d_lossH, (double)smem[0]);
}

// ---------------- fused setup: scalars + starts ----------------
__global__ void k_setup(const float* __restrict__ t,
                        const float* __restrict__ gph,
                        const float* __restrict__ gpp,
                        const int* __restrict__ idx, int B, int N) {
    const int nbs = (B + 255) / 256;
    int gid = blockIdx.x;
    if (gid < nbs) {
        int b = gid * 256 + threadIdx.x;
        if (b == 0) { d_start[B] = N; d_lossH = 0.0; d_lossP = 0.0; }
        if (b >= B) return;
        float tb  = t[b];
        float sph = softplusf(gph[0]);
        float spp = softplusf(gpp[0]);
        float gh  = 0.1f + sph * tb;
        float gp  = 0.1f + spp * tb;
        float sig = 0.1f + 0.9f * tb;
        float omt = 1.f - tb;
        float a   = 0.2f + 0.8f * tb;
        float bb  = 0.1f * tb;
        float s   = (1.f + (0.9f + 0.5f*gh*gh/sig) * omt / sig) / gh;
        float* g = &d_gpar[b * GS];
        g[0]=tb; g[1]=omt; g[2]=sig; g[3]=a; g[4]=bb; g[5]=1.f/a;
        g[6]=gp; g[7]=0.5f*gp*gp; g[8]=s;
    } else {
        int n = (gid - nbs) * 256 + threadIdx.x;
        if (n >= N) return;
        int b = idx[n];
        if (n == 0 || idx[n-1] != b) d_start[b] = n;
    }
}

__global__ void k_final(float* out, int N) {
    out[0] = (float)(d_lossH / ((double)N * 256.0));
    out[1] = (float)(d_lossP / ((double)N * 3.0));
}

// ---------------- launch ----------------
extern "C" void kernel_launch(void* const* d_in, const int* in_sizes, int n_in,
                              void* d_out, int out_size) {
    const float* t      = (const float*)d_in[0];
    const float* h      = (const float*)d_in[1];
    const float* pos    = (const float*)d_in[2];
    const float* eps_h  = (const float*)d_in[3];
    const float* eps_p  = (const float*)d_in[4];
    const float* gph    = (const float*)d_in[5];
    const float* gpp    = (const float*)d_in[6];
    const float* W_mu   = (const float*)d_in[7];
    const float* W_r1   = (const float*)d_in[8];
    const float* W_r2   = (const float*)d_in[9];
    const int*   idx    = (const int*)d_in[10];

    int B = in_sizes[0];
    int N = in_sizes[10];
    float* out = (float*)d_out;

    int nbs = (B + 255) / 256;
    int nbn = (N + 255) / 256;
    k_setup<<<nbs + nbn, 256>>>(t, gph, gpp, idx, B, N);

    int mt = (N + 127) / 128;
    k_fused1<<<8 + 2 * mt + B, 256>>>(h, W_mu, eps_h, idx, W_r2, pos, eps_p, N, mt);
    k_gemm2<<<dim3(4, mt), 256>>>(W_r1, N);
    k_gemm34<<<dim3(2, mt), 256>>>(idx, N);

    k_final<<<1, 1>>>(out, N);
}